// round 12
// baseline (speedup 1.0000x reference)
#include <cuda_runtime.h>
#include <cuda_bf16.h>
#include <cuda_pipeline.h>
#include <math.h>
#include <cstdint>

// B=32, IU=128, OU=128, ID=64, VD=64
// mean-votes GEMM: mv[b][n] = (1/128) sum_{i,e} x[b,i,e] * W[i*524288 + n*64 + e]
// Fat kernel: bf16 mma.sync GEMM (y<4) + prep (y==4). attn1 fuses LN+K1 (block-local) + Q2 proj.

// ---------------- scratch ----------------
__device__ float g_part[4][32 * 8192];   // K-split partials
__device__ float g_q[32 * 128 * 64];     // Q1, then Q2
__device__ float g_k2[32 * 128 * 64];    // K2
__device__ float g_agg[32 * 128 * 64];   // aggregated_value
__device__ float g_wvo[2][64 * 64];
__device__ float g_bvo[2][64];

// ---------------- bf16 helpers ----------------
__device__ __forceinline__ unsigned pack_bf16(float lo, float hi) {
    unsigned r;
    asm("cvt.rn.bf16x2.f32 %0, %1, %2;" : "=r"(r) : "f"(hi), "f"(lo));  // first src -> high half
    return r;
}
#define MMA_BF16(d, a, b)                                                  \
    asm("mma.sync.aligned.m16n8k16.row.col.f32.bf16.bf16.f32 "             \
        "{%0,%1,%2,%3}, {%4,%5,%6,%7}, {%8,%9}, {%0,%1,%2,%3};"            \
        : "+f"((d)[0]), "+f"((d)[1]), "+f"((d)[2]), "+f"((d)[3])           \
        : "r"((a)[0]), "r"((a)[1]), "r"((a)[2]), "r"((a)[3]),              \
          "r"((b)[0]), "r"((b)[1]))

// ---------------- fat kernel: GEMM (y<4) + prep (y==4) ----------------
constexpr int RSTR = 40;
constexpr int STG_F = 256 * RSTR + 32 * RSTR;        // 11520 floats / stage
constexpr int GEMM_SMEM = 4 * STG_F * 4;             // 184320 B

__global__ __launch_bounds__(512, 1)
void fat_kernel(const float* __restrict__ X, const float* __restrict__ W,
                const float* __restrict__ wq1, const float* __restrict__ bq1,
                const float* __restrict__ wk2, const float* __restrict__ bk2,
                const float* wv1, const float* wo1, const float* bv1, const float* bo1,
                const float* wv2, const float* wo2, const float* bv2, const float* bo2) {
    extern __shared__ float sm[];
    const int tid = threadIdx.x;

    if (blockIdx.y == 4) {
        // ---------- prep path: projections (x -> Q1, K2) + wvo fold ----------
        float* ws  = sm;                 // 4096
        float* ins = sm + 4096;          // 256 x 65
        const int bx = blockIdx.x;
        const bool isA = bx < 16;
        const float* win = isA ? wq1 : wk2;
        const float* bin = isA ? bq1 : bk2;
        float* outp = isA ? g_q : g_k2;
        const int row0 = (isA ? bx : bx - 16) * 256;

        for (int idx = tid; idx < 4096; idx += 512) ws[idx] = win[idx];
        for (int idx = tid; idx < 16384; idx += 512)
            ins[(idx >> 6) * 65 + (idx & 63)] = X[(size_t)row0 * 64 + idx];
        __syncthreads();

        const int lane = tid & 31, j0 = ((tid >> 5) & 7) * 8, half = tid >> 8;
        #pragma unroll
        for (int rr = 0; rr < 4; ++rr) {
            const int row = half * 128 + rr * 32 + lane;
            float acc[8];
            #pragma unroll
            for (int k = 0; k < 8; ++k) acc[k] = bin[j0 + k];
            #pragma unroll 8
            for (int e = 0; e < 64; ++e) {
                float xv = ins[row * 65 + e];
                float4 w1 = *(const float4*)&ws[e * 64 + j0];
                float4 w2 = *(const float4*)&ws[e * 64 + j0 + 4];
                acc[0] += xv * w1.x; acc[1] += xv * w1.y; acc[2] += xv * w1.z; acc[3] += xv * w1.w;
                acc[4] += xv * w2.x; acc[5] += xv * w2.y; acc[6] += xv * w2.z; acc[7] += xv * w2.w;
            }
            float* o = outp + (size_t)(row0 + row) * 64 + j0;
            *(float4*)o       = make_float4(acc[0], acc[1], acc[2], acc[3]);
            *(float4*)(o + 4) = make_float4(acc[4], acc[5], acc[6], acc[7]);
        }

        if (bx == 0 || bx == 16) {       // wvo = wv@wo, bvo = bv@wo + bo
            const int a = isA ? 0 : 1;
            const float* wv = a ? wv2 : wv1; const float* wo = a ? wo2 : wo1;
            const float* bv = a ? bv2 : bv1; const float* bo = a ? bo2 : bo1;
            __syncthreads();
            for (int idx = tid; idx < 4096; idx += 512) ws[idx] = wo[idx];
            __syncthreads();
            const int j = tid & 63, dblk = tid >> 6;
            #pragma unroll
            for (int k = 0; k < 8; ++k) {
                const int d = dblk * 8 + k;
                float s = 0.f;
                #pragma unroll
                for (int e = 0; e < 64; ++e) s += wv[d * 64 + e] * ws[e * 64 + j];
                g_wvo[a][d * 64 + j] = s;
            }
            if (tid < 64) {
                float s = 0.f;
                #pragma unroll
                for (int e = 0; e < 64; ++e) s += bv[e] * ws[e * 64 + tid];
                g_bvo[a][tid] = s + bo[tid];
            }
        }
        return;
    }

    // ---------- GEMM path ----------
    const int lane = tid & 31, wid = tid >> 5;
    const int n0 = blockIdx.x * 256;
    const int ks = blockIdx.y;
    const int i0 = ks * 32;

    auto load_stage = [&](int st) {
        float* Ws = sm + (st & 3) * STG_F;
        float* Xs = Ws + 256 * RSTR;
        const int i  = i0 + (st >> 1);
        const int e0 = (st & 1) * 32;
        const float* wb = W + (size_t)i * 524288 + (size_t)n0 * 64 + e0;
        #pragma unroll
        for (int c = tid; c < 2048; c += 512) {
            int n = c >> 3, g = c & 7;
            __pipeline_memcpy_async(&Ws[n * RSTR + g * 4], wb + n * 64 + g * 4, 16);
        }
        if (tid < 256) {
            int b = tid >> 3, g = tid & 7;
            __pipeline_memcpy_async(&Xs[b * RSTR + g * 4],
                X + (size_t)b * 8192 + (size_t)i * 64 + e0 + g * 4, 16);
        }
        __pipeline_commit();
    };

    load_stage(0); load_stage(1); load_stage(2);

    float acc[8][4];
    #pragma unroll
    for (int g = 0; g < 8; ++g)
        #pragma unroll
        for (int k = 0; k < 4; ++k) acc[g][k] = 0.f;

    const int r = lane >> 2, c = lane & 3;
    const int ng = wid & 3;
    const int kg = (wid >> 2) & 1;
    const int mg = wid >> 3;
    const int m0 = mg * 16 + r;
    const int k0 = kg * 16 + 2 * c;

    for (int it = 0; it < 64; ++it) {
        if (it <= 61)      __pipeline_wait_prior(2);
        else if (it == 62) __pipeline_wait_prior(1);
        else               __pipeline_wait_prior(0);
        __syncthreads();
        if (it + 3 < 64) load_stage(it + 3);

        const float* Ws = sm + (it & 3) * STG_F;
        const float* Xs = Ws + 256 * RSTR;

        unsigned a[4];
        {
            float2 p0 = *(const float2*)&Xs[m0 * RSTR + k0];
            float2 p1 = *(const float2*)&Xs[(m0 + 8) * RSTR + k0];
            float2 p2 = *(const float2*)&Xs[m0 * RSTR + k0 + 8];
            float2 p3 = *(const float2*)&Xs[(m0 + 8) * RSTR + k0 + 8];
            a[0] = pack_bf16(p0.x, p0.y);
            a[1] = pack_bf16(p1.x, p1.y);
            a[2] = pack_bf16(p2.x, p2.y);
            a[3] = pack_bf16(p3.x, p3.y);
        }
        #pragma unroll
        for (int g = 0; g < 8; ++g) {
            const int nrow = ng * 64 + g * 8 + r;
            float2 q0 = *(const float2*)&Ws[nrow * RSTR + k0];
            float2 q1 = *(const float2*)&Ws[nrow * RSTR + k0 + 8];
            unsigned bf[2];
            bf[0] = pack_bf16(q0.x, q0.y);
            bf[1] = pack_bf16(q1.x, q1.y);
            MMA_BF16(acc[g], a, bf);
        }
    }
    __syncthreads();

    float* red = sm;
    if (kg == 1) {
        #pragma unroll
        for (int g = 0; g < 8; ++g) {
            const int nc = ng * 64 + g * 8 + 2 * c;
            *(float2*)&red[m0 * 256 + nc]       = make_float2(acc[g][0], acc[g][1]);
            *(float2*)&red[(m0 + 8) * 256 + nc] = make_float2(acc[g][2], acc[g][3]);
        }
    }
    __syncthreads();
    if (kg == 0) {
        float* dst = g_part[ks];
        #pragma unroll
        for (int g = 0; g < 8; ++g) {
            const int nc = ng * 64 + g * 8 + 2 * c;
            *(float2*)&dst[(size_t)m0 * 8192 + n0 + nc] = make_float2(
                acc[g][0] + red[m0 * 256 + nc],
                acc[g][1] + red[m0 * 256 + nc + 1]);
            *(float2*)&dst[(size_t)(m0 + 8) * 8192 + n0 + nc] = make_float2(
                acc[g][2] + red[(m0 + 8) * 256 + nc],
                acc[g][3] + red[(m0 + 8) * 256 + nc + 1]);
        }
    }
}

// ---------------- attention kernel (optionally fused LN+K1, optionally fused Q2) ----------------
// smem: ks[128x68] | vs[128x68] | w1s(wvo)[4096] | w2s(wq2)[4096] | sc[32x132] | qs[32x68]
constexpr int AS_K  = 0;
constexpr int AS_V  = 128 * 68;                 // 8704
constexpr int AS_W1 = AS_V + 128 * 68;          // 17408
constexpr int AS_W2 = AS_W1 + 4096;             // 21504
constexpr int AS_SC = AS_W2 + 4096;             // 25600
constexpr int AS_QS = AS_SC + 32 * 132;         // 29824
constexpr int ATTN_SMEM = (AS_QS + 32 * 68) * 4;   // 128000 B

__global__ __launch_bounds__(512)
void attn_kernel(const float* __restrict__ Q, const float* __restrict__ Kp,
                 const float* __restrict__ Vsrc,
                 const float* __restrict__ wvo, const float* __restrict__ bvo,
                 float* scores_out, float* val_out, float* val_out2,
                 const float* __restrict__ wq2, const float* __restrict__ bq2,
                 float* __restrict__ q2_out,
                 const float* __restrict__ lng, const float* __restrict__ lnb,
                 const float* __restrict__ wk1, const float* __restrict__ bk1) {
    extern __shared__ float asmem[];
    float* ks  = asmem + AS_K;
    float* vs  = asmem + AS_V;
    float* w1s = asmem + AS_W1;
    float* w2s = asmem + AS_W2;
    float* sc  = asmem + AS_SC;
    float* qs  = asmem + AS_QS;
    const int t = threadIdx.x;
    const int w = t >> 5, lane = t & 31;
    const int b = blockIdx.y, qt = blockIdx.x;
    const int q0 = qt * 32;
    const int q = t >> 4, jg = t & 15;     // 16 threads per q-row

    // ---- entry loads ----
    const float* Qb = Q + b * 8192 + q0 * 64;
    for (int idx = t; idx < 2048; idx += 512) qs[(idx >> 6) * 68 + (idx & 63)] = Qb[idx];
    for (int idx = t; idx < 4096; idx += 512) w1s[idx] = wvo[idx];
    if (wq2) for (int idx = t; idx < 4096; idx += 512) w2s[idx] = wq2[idx];

    if (wk1) {
        // ---- fused LN + K1 projection (block-local; validated in R11) ----
        for (int idx = t; idx < 4096; idx += 512) sc[idx] = wk1[idx];   // wk1 staged in sc
        // LN of mean-votes for all 128 rows of batch b -> vs (temp)
        #pragma unroll
        for (int rr = 0; rr < 8; ++rr) {
            const int o = rr * 16 + w;
            const int base = (b * 128 + o) * 64;
            float v0 = (g_part[0][base + lane] + g_part[1][base + lane] +
                        g_part[2][base + lane] + g_part[3][base + lane]) * (1.0f / 128.0f);
            float v1 = (g_part[0][base + lane + 32] + g_part[1][base + lane + 32] +
                        g_part[2][base + lane + 32] + g_part[3][base + lane + 32]) * (1.0f / 128.0f);
            float s  = v0 + v1;
            float sq = v0 * v0 + v1 * v1;
            #pragma unroll
            for (int off = 16; off; off >>= 1) {
                s  += __shfl_xor_sync(0xffffffffu, s,  off);
                sq += __shfl_xor_sync(0xffffffffu, sq, off);
            }
            float mean = s * (1.0f / 64.0f);
            float var  = sq * (1.0f / 64.0f) - mean * mean;
            float rstd = rsqrtf(var + 1e-6f);
            vs[o * 68 + lane]      = (v0 - mean) * rstd * lng[lane]      + lnb[lane];
            vs[o * 68 + lane + 32] = (v1 - mean) * rstd * lng[lane + 32] + lnb[lane + 32];
        }
        __syncthreads();
        // K1 = LN @ wk1 + bk1 -> ks (thread: 1 row, 16 cols)
        {
            const int r = t >> 2, j0 = (t & 3) * 16;
            float acc[16];
            #pragma unroll
            for (int i = 0; i < 16; ++i) acc[i] = bk1[j0 + i];
            #pragma unroll 8
            for (int e = 0; e < 64; ++e) {
                float lnv = vs[r * 68 + e];
                #pragma unroll
                for (int v4 = 0; v4 < 4; ++v4) {
                    float4 wv = *(const float4*)&sc[e * 64 + j0 + v4 * 4];
                    acc[v4 * 4 + 0] += lnv * wv.x; acc[v4 * 4 + 1] += lnv * wv.y;
                    acc[v4 * 4 + 2] += lnv * wv.z; acc[v4 * 4 + 3] += lnv * wv.w;
                }
            }
            #pragma unroll
            for (int v4 = 0; v4 < 4; ++v4)
                *(float4*)&ks[r * 68 + j0 + v4 * 4] =
                    make_float4(acc[v4 * 4], acc[v4 * 4 + 1], acc[v4 * 4 + 2], acc[v4 * 4 + 3]);
        }
        __syncthreads();   // all vs reads done before V overwrites; ks fully written
        // load V into vs
        const float* Vb = Vsrc + b * 8192;
        for (int idx = t; idx < 8192; idx += 512) vs[(idx >> 6) * 68 + (idx & 63)] = Vb[idx];
        __syncthreads();
    } else {
        // ---- plain path: K and V from global ----
        const float* Kb = Kp + b * 8192;
        const float* Vb = Vsrc + b * 8192;
        for (int idx = t; idx < 8192; idx += 512) {
            ks[(idx >> 6) * 68 + (idx & 63)] = Kb[idx];
            vs[(idx >> 6) * 68 + (idx & 63)] = Vb[idx];
        }
        __syncthreads();
    }

    // ---- phase 1: scores + softmax. 16 threads/q-row, 8 k's each ----
    float acc[8];
    #pragma unroll
    for (int rep = 0; rep < 8; ++rep) acc[rep] = 0.f;
    #pragma unroll
    for (int e4 = 0; e4 < 16; ++e4) {
        float4 qv = *(const float4*)&qs[q * 68 + e4 * 4];
        #pragma unroll
        for (int rep = 0; rep < 8; ++rep) {
            float4 kvv = *(const float4*)&ks[(jg + 16 * rep) * 68 + e4 * 4];
            acc[rep] += qv.x * kvv.x + qv.y * kvv.y + qv.z * kvv.z + qv.w * kvv.w;
        }
    }
    float m = -1e30f;
    #pragma unroll
    for (int rep = 0; rep < 8; ++rep) { acc[rep] *= 0.125f; m = fmaxf(m, acc[rep]); }
    #pragma unroll
    for (int off = 1; off < 16; off <<= 1) m = fmaxf(m, __shfl_xor_sync(0xffffffffu, m, off));
    float ssum = 0.f;
    #pragma unroll
    for (int rep = 0; rep < 8; ++rep) { acc[rep] = __expf(acc[rep] - m); ssum += acc[rep]; }
    #pragma unroll
    for (int off = 1; off < 16; off <<= 1) ssum += __shfl_xor_sync(0xffffffffu, ssum, off);
    const float inv = 1.0f / ssum;
    float* so = scores_out ? scores_out + b * 16384 + (q0 + q) * 128 : nullptr;
    #pragma unroll
    for (int rep = 0; rep < 8; ++rep) {
        float p = acc[rep] * inv;
        sc[q * 132 + jg + 16 * rep] = p;
        if (so) so[jg + 16 * rep] = p;
    }
    __syncthreads();

    // ---- phase 2: ctx = S @ V. 16 threads/q, 4 d's each ----
    {
        float c0 = 0.f, c1 = 0.f, c2 = 0.f, c3 = 0.f;
        #pragma unroll 8
        for (int k4 = 0; k4 < 32; ++k4) {
            float4 p = *(const float4*)&sc[q * 132 + k4 * 4];
            float4 va = *(const float4*)&vs[(k4 * 4 + 0) * 68 + jg * 4];
            float4 vb = *(const float4*)&vs[(k4 * 4 + 1) * 68 + jg * 4];
            float4 vc = *(const float4*)&vs[(k4 * 4 + 2) * 68 + jg * 4];
            float4 vd = *(const float4*)&vs[(k4 * 4 + 3) * 68 + jg * 4];
            c0 += p.x * va.x + p.y * vb.x + p.z * vc.x + p.w * vd.x;
            c1 += p.x * va.y + p.y * vb.y + p.z * vc.y + p.w * vd.y;
            c2 += p.x * va.z + p.y * vb.z + p.z * vc.z + p.w * vd.z;
            c3 += p.x * va.w + p.y * vb.w + p.z * vc.w + p.w * vd.w;
        }
        __syncthreads();
        *(float4*)&qs[q * 68 + jg * 4] = make_float4(c0, c1, c2, c3);  // Q dead -> ctx
    }
    __syncthreads();

    // ---- phase 3: out = ctx @ wvo + bvo ----
    float o[4];
    #pragma unroll
    for (int i = 0; i < 4; ++i) o[i] = bvo[jg * 4 + i];
    #pragma unroll 4
    for (int d4 = 0; d4 < 16; ++d4) {
        float4 cv = *(const float4*)&qs[q * 68 + d4 * 4];
        float4 wa = *(const float4*)&w1s[(d4 * 4 + 0) * 64 + jg * 4];
        float4 wb = *(const float4*)&w1s[(d4 * 4 + 1) * 64 + jg * 4];
        float4 wc = *(const float4*)&w1s[(d4 * 4 + 2) * 64 + jg * 4];
        float4 wd = *(const float4*)&w1s[(d4 * 4 + 3) * 64 + jg * 4];
        o[0] += cv.x * wa.x + cv.y * wb.x + cv.z * wc.x + cv.w * wd.x;
        o[1] += cv.x * wa.y + cv.y * wb.y + cv.z * wc.y + cv.w * wd.y;
        o[2] += cv.x * wa.z + cv.y * wb.z + cv.z * wc.z + cv.w * wd.z;
        o[3] += cv.x * wa.w + cv.y * wb.w + cv.z * wc.w + cv.w * wd.w;
    }
    const size_t ooff = (size_t)b * 8192 + (size_t)(q0 + q) * 64 + jg * 4;
    *(float4*)&val_out[ooff] = make_float4(o[0], o[1], o[2], o[3]);
    if (val_out2) *(float4*)&val_out2[ooff] = make_float4(o[0], o[1], o[2], o[3]);

    // ---- phase 4: fused Q2 projection ----
    if (q2_out) {
        *(float4*)&sc[q * 68 + jg * 4] = make_float4(o[0], o[1], o[2], o[3]);
        __syncthreads();
        float o2[4];
        #pragma unroll
        for (int i = 0; i < 4; ++i) o2[i] = bq2[jg * 4 + i];
        #pragma unroll 4
        for (int d4 = 0; d4 < 16; ++d4) {
            float4 cv = *(const float4*)&sc[q * 68 + d4 * 4];
            float4 wa = *(const float4*)&w2s[(d4 * 4 + 0) * 64 + jg * 4];
            float4 wb = *(const float4*)&w2s[(d4 * 4 + 1) * 64 + jg * 4];
            float4 wc = *(const float4*)&w2s[(d4 * 4 + 2) * 64 + jg * 4];
            float4 wd = *(const float4*)&w2s[(d4 * 4 + 3) * 64 + jg * 4];
            o2[0] += cv.x * wa.x + cv.y * wb.x + cv.z * wc.x + cv.w * wd.x;
            o2[1] += cv.x * wa.y + cv.y * wb.y + cv.z * wc.y + cv.w * wd.y;
            o2[2] += cv.x * wa.z + cv.y * wb.z + cv.z * wc.z + cv.w * wd.z;
            o2[3] += cv.x * wa.w + cv.y * wb.w + cv.z * wc.w + cv.w * wd.w;
        }
        *(float4*)&q2_out[ooff] = make_float4(o2[0], o2[1], o2[2], o2[3]);
    }
}

extern "C" void kernel_launch(void* const* d_in, const int* in_sizes, int n_in,
                              void* d_out, int out_size) {
    const float* x      = (const float*)d_in[0];
    const float* W_vote = (const float*)d_in[1];
    const float* ln_g   = (const float*)d_in[2];
    const float* ln_b   = (const float*)d_in[3];
    const float* wq1 = (const float*)d_in[4];  const float* bq1 = (const float*)d_in[5];
    const float* wk1 = (const float*)d_in[6];  const float* bk1 = (const float*)d_in[7];
    const float* wv1 = (const float*)d_in[8];  const float* bv1 = (const float*)d_in[9];
    const float* wo1 = (const float*)d_in[10]; const float* bo1 = (const float*)d_in[11];
    const float* wq2 = (const float*)d_in[12]; const float* bq2 = (const float*)d_in[13];
    const float* wk2 = (const float*)d_in[14]; const float* bk2 = (const float*)d_in[15];
    const float* wv2 = (const float*)d_in[16]; const float* bv2 = (const float*)d_in[17];
    const float* wo2 = (const float*)d_in[18]; const float* bo2 = (const float*)d_in[19];
    float* out = (float*)d_out;

    float* out_diff = out;
    float* out_agg  = (out_size >= 524288)  ? out + 262144  : nullptr;
    float* out_fat  = (out_size >= 1048576) ? out + 524288  : nullptr;
    float* out_bat  = (out_size >= 1572864) ? out + 1048576 : nullptr;

    static int smem_set = 0;
    if (!smem_set) {
        cudaFuncSetAttribute(fat_kernel,
                             cudaFuncAttributeMaxDynamicSharedMemorySize, GEMM_SMEM);
        cudaFuncSetAttribute(attn_kernel,
                             cudaFuncAttributeMaxDynamicSharedMemorySize, ATTN_SMEM);
        smem_set = 1;
    }

    float *p_q, *p_k2, *p_agg, *p_wvo, *p_bvo;
    cudaGetSymbolAddress((void**)&p_q,   g_q);
    cudaGetSymbolAddress((void**)&p_k2,  g_k2);
    cudaGetSymbolAddress((void**)&p_agg, g_agg);
    cudaGetSymbolAddress((void**)&p_wvo, g_wvo);
    cudaGetSymbolAddress((void**)&p_bvo, g_bvo);

    // 1) fat kernel: bf16 GEMM (y=0..3) + Q1/K2 projections + wvo folds (y=4)
    fat_kernel<<<dim3(32, 5), 512, GEMM_SMEM>>>(x, W_vote, wq1, bq1, wk2, bk2,
                                                wv1, wo1, bv1, bo1,
                                                wv2, wo2, bv2, bo2);
    // 2) forward attention: fused LN+K1 (block-local) + attn1 + fused Q2 -> p_q
    attn_kernel<<<dim3(4, 32), 512, ATTN_SMEM>>>(p_q, nullptr, x, p_wvo, p_bvo,
                                                 out_fat, p_agg, out_agg, wq2, bq2, p_q,
                                                 ln_g, ln_b, wk1, bk1);
    // 3) feedback attention (plain path)
    attn_kernel<<<dim3(4, 32), 512, ATTN_SMEM>>>(p_q, p_k2, p_agg, p_wvo + 4096, p_bvo + 64,
                                                 out_bat, out_diff, nullptr, nullptr, nullptr, nullptr,
                                                 nullptr, nullptr, nullptr, nullptr);
}

// round 15
// speedup vs baseline: 1.1837x; 1.1837x over previous
#include <cuda_runtime.h>
#include <cuda_bf16.h>
#include <cuda_pipeline.h>
#include <math.h>
#include <cstdint>

// B=32, IU=128, OU=128, ID=64, VD=64
// mean-votes GEMM: mv[b][n] = (1/128) sum_{i,e} x[b,i,e] * W[i*524288 + n*64 + e]
// Fat kernel: bf16 mma.sync GEMM (y<4) + prep (y==4). Attention: 256 blocks, 2/SM co-resident.

// ---------------- scratch ----------------
__device__ float g_part[4][32 * 8192];   // K-split partials
__device__ float g_q[32 * 128 * 64];     // Q1, then Q2
__device__ float g_k[32 * 128 * 64];     // K1
__device__ float g_k2[32 * 128 * 64];    // K2
__device__ float g_agg[32 * 128 * 64];   // aggregated_value
__device__ float g_wvo[2][64 * 64];
__device__ float g_bvo[2][64];

// ---------------- bf16 helpers ----------------
__device__ __forceinline__ unsigned pack_bf16(float lo, float hi) {
    unsigned r;
    asm("cvt.rn.bf16x2.f32 %0, %1, %2;" : "=r"(r) : "f"(hi), "f"(lo));  // first src -> high half
    return r;
}
#define MMA_BF16(d, a, b)                                                  \
    asm("mma.sync.aligned.m16n8k16.row.col.f32.bf16.bf16.f32 "             \
        "{%0,%1,%2,%3}, {%4,%5,%6,%7}, {%8,%9}, {%0,%1,%2,%3};"            \
        : "+f"((d)[0]), "+f"((d)[1]), "+f"((d)[2]), "+f"((d)[3])           \
        : "r"((a)[0]), "r"((a)[1]), "r"((a)[2]), "r"((a)[3]),              \
          "r"((b)[0]), "r"((b)[1]))

// ---------------- fat kernel: GEMM (y<4) + prep (y==4) ----------------
constexpr int RSTR = 40;
constexpr int STG_F = 256 * RSTR + 32 * RSTR;        // 11520 floats / stage
constexpr int GEMM_SMEM = 4 * STG_F * 4;             // 184320 B

__global__ __launch_bounds__(512, 1)
void fat_kernel(const float* __restrict__ X, const float* __restrict__ W,
                const float* __restrict__ wq1, const float* __restrict__ bq1,
                const float* __restrict__ wk2, const float* __restrict__ bk2,
                const float* wv1, const float* wo1, const float* bv1, const float* bo1,
                const float* wv2, const float* wo2, const float* bv2, const float* bo2) {
    extern __shared__ float sm[];
    const int tid = threadIdx.x;

    if (blockIdx.y == 4) {
        // ---------- prep path: projections (x -> Q1, K2) + wvo fold ----------
        float* ws  = sm;                 // 4096
        float* ins = sm + 4096;          // 256 x 65
        const int bx = blockIdx.x;
        const bool isA = bx < 16;
        const float* win = isA ? wq1 : wk2;
        const float* bin = isA ? bq1 : bk2;
        float* outp = isA ? g_q : g_k2;
        const int row0 = (isA ? bx : bx - 16) * 256;

        for (int idx = tid; idx < 4096; idx += 512) ws[idx] = win[idx];
        for (int idx = tid; idx < 16384; idx += 512)
            ins[(idx >> 6) * 65 + (idx & 63)] = X[(size_t)row0 * 64 + idx];
        __syncthreads();

        const int lane = tid & 31, j0 = ((tid >> 5) & 7) * 8, half = tid >> 8;
        #pragma unroll
        for (int rr = 0; rr < 4; ++rr) {
            const int row = half * 128 + rr * 32 + lane;
            float acc[8];
            #pragma unroll
            for (int k = 0; k < 8; ++k) acc[k] = bin[j0 + k];
            #pragma unroll 8
            for (int e = 0; e < 64; ++e) {
                float xv = ins[row * 65 + e];
                float4 w1 = *(const float4*)&ws[e * 64 + j0];
                float4 w2 = *(const float4*)&ws[e * 64 + j0 + 4];
                acc[0] += xv * w1.x; acc[1] += xv * w1.y; acc[2] += xv * w1.z; acc[3] += xv * w1.w;
                acc[4] += xv * w2.x; acc[5] += xv * w2.y; acc[6] += xv * w2.z; acc[7] += xv * w2.w;
            }
            float* o = outp + (size_t)(row0 + row) * 64 + j0;
            *(float4*)o       = make_float4(acc[0], acc[1], acc[2], acc[3]);
            *(float4*)(o + 4) = make_float4(acc[4], acc[5], acc[6], acc[7]);
        }

        if (bx == 0 || bx == 16) {       // wvo = wv@wo, bvo = bv@wo + bo
            const int a = isA ? 0 : 1;
            const float* wv = a ? wv2 : wv1; const float* wo = a ? wo2 : wo1;
            const float* bv = a ? bv2 : bv1; const float* bo = a ? bo2 : bo1;
            __syncthreads();
            for (int idx = tid; idx < 4096; idx += 512) ws[idx] = wo[idx];
            __syncthreads();
            const int j = tid & 63, dblk = tid >> 6;
            #pragma unroll
            for (int k = 0; k < 8; ++k) {
                const int d = dblk * 8 + k;
                float s = 0.f;
                #pragma unroll
                for (int e = 0; e < 64; ++e) s += wv[d * 64 + e] * ws[e * 64 + j];
                g_wvo[a][d * 64 + j] = s;
            }
            if (tid < 64) {
                float s = 0.f;
                #pragma unroll
                for (int e = 0; e < 64; ++e) s += bv[e] * ws[e * 64 + tid];
                g_bvo[a][tid] = s + bo[tid];
            }
        }
        return;
    }

    // ---------- GEMM path ----------
    const int lane = tid & 31, wid = tid >> 5;
    const int n0 = blockIdx.x * 256;
    const int ks = blockIdx.y;
    const int i0 = ks * 32;

    auto load_stage = [&](int st) {
        float* Ws = sm + (st & 3) * STG_F;
        float* Xs = Ws + 256 * RSTR;
        const int i  = i0 + (st >> 1);
        const int e0 = (st & 1) * 32;
        const float* wb = W + (size_t)i * 524288 + (size_t)n0 * 64 + e0;
        #pragma unroll
        for (int c = tid; c < 2048; c += 512) {
            int n = c >> 3, g = c & 7;
            __pipeline_memcpy_async(&Ws[n * RSTR + g * 4], wb + n * 64 + g * 4, 16);
        }
        if (tid < 256) {
            int b = tid >> 3, g = tid & 7;
            __pipeline_memcpy_async(&Xs[b * RSTR + g * 4],
                X + (size_t)b * 8192 + (size_t)i * 64 + e0 + g * 4, 16);
        }
        __pipeline_commit();
    };

    load_stage(0); load_stage(1); load_stage(2);

    float acc[8][4];
    #pragma unroll
    for (int g = 0; g < 8; ++g)
        #pragma unroll
        for (int k = 0; k < 4; ++k) acc[g][k] = 0.f;

    const int r = lane >> 2, c = lane & 3;
    const int ng = wid & 3;
    const int kg = (wid >> 2) & 1;
    const int mg = wid >> 3;
    const int m0 = mg * 16 + r;
    const int k0 = kg * 16 + 2 * c;

    for (int it = 0; it < 64; ++it) {
        if (it <= 61)      __pipeline_wait_prior(2);
        else if (it == 62) __pipeline_wait_prior(1);
        else               __pipeline_wait_prior(0);
        __syncthreads();
        if (it + 3 < 64) load_stage(it + 3);

        const float* Ws = sm + (it & 3) * STG_F;
        const float* Xs = Ws + 256 * RSTR;

        unsigned a[4];
        {
            float2 p0 = *(const float2*)&Xs[m0 * RSTR + k0];
            float2 p1 = *(const float2*)&Xs[(m0 + 8) * RSTR + k0];
            float2 p2 = *(const float2*)&Xs[m0 * RSTR + k0 + 8];
            float2 p3 = *(const float2*)&Xs[(m0 + 8) * RSTR + k0 + 8];
            a[0] = pack_bf16(p0.x, p0.y);
            a[1] = pack_bf16(p1.x, p1.y);
            a[2] = pack_bf16(p2.x, p2.y);
            a[3] = pack_bf16(p3.x, p3.y);
        }
        #pragma unroll
        for (int g = 0; g < 8; ++g) {
            const int nrow = ng * 64 + g * 8 + r;
            float2 q0 = *(const float2*)&Ws[nrow * RSTR + k0];
            float2 q1 = *(const float2*)&Ws[nrow * RSTR + k0 + 8];
            unsigned bf[2];
            bf[0] = pack_bf16(q0.x, q0.y);
            bf[1] = pack_bf16(q1.x, q1.y);
            MMA_BF16(acc[g], a, bf);
        }
    }
    __syncthreads();

    float* red = sm;
    if (kg == 1) {
        #pragma unroll
        for (int g = 0; g < 8; ++g) {
            const int nc = ng * 64 + g * 8 + 2 * c;
            *(float2*)&red[m0 * 256 + nc]       = make_float2(acc[g][0], acc[g][1]);
            *(float2*)&red[(m0 + 8) * 256 + nc] = make_float2(acc[g][2], acc[g][3]);
        }
    }
    __syncthreads();
    if (kg == 0) {
        float* dst = g_part[ks];
        #pragma unroll
        for (int g = 0; g < 8; ++g) {
            const int nc = ng * 64 + g * 8 + 2 * c;
            *(float2*)&dst[(size_t)m0 * 8192 + n0 + nc] = make_float2(
                acc[g][0] + red[m0 * 256 + nc],
                acc[g][1] + red[m0 * 256 + nc + 1]);
            *(float2*)&dst[(size_t)(m0 + 8) * 8192 + n0 + nc] = make_float2(
                acc[g][2] + red[(m0 + 8) * 256 + nc],
                acc[g][3] + red[(m0 + 8) * 256 + nc + 1]);
        }
    }
}

// ---------------- fused: K-split reduce + 1/128 + layernorm + K1 projection ----------------
__global__ __launch_bounds__(256)
void ln_k1_kernel(const float* __restrict__ lng, const float* __restrict__ lnb,
                  const float* __restrict__ wk1, const float* __restrict__ bk1) {
    __shared__ float ws[4096];
    __shared__ float rows[8][68];
    const int tid = threadIdx.x;
    const int w = tid >> 5, t = tid & 31;
    const int row = blockIdx.x * 8 + w;
    const int base = row * 64;

    for (int idx = tid; idx < 4096; idx += 256) ws[idx] = wk1[idx];

    float v0 = (g_part[0][base + t] + g_part[1][base + t] +
                g_part[2][base + t] + g_part[3][base + t]) * (1.0f / 128.0f);
    float v1 = (g_part[0][base + t + 32] + g_part[1][base + t + 32] +
                g_part[2][base + t + 32] + g_part[3][base + t + 32]) * (1.0f / 128.0f);
    float s  = v0 + v1;
    float sq = v0 * v0 + v1 * v1;
    #pragma unroll
    for (int off = 16; off; off >>= 1) {
        s  += __shfl_xor_sync(0xffffffffu, s,  off);
        sq += __shfl_xor_sync(0xffffffffu, sq, off);
    }
    float mean = s * (1.0f / 64.0f);
    float var  = sq * (1.0f / 64.0f) - mean * mean;
    float rstd = rsqrtf(var + 1e-6f);
    rows[w][t]      = (v0 - mean) * rstd * lng[t]      + lnb[t];
    rows[w][t + 32] = (v1 - mean) * rstd * lng[t + 32] + lnb[t + 32];
    __syncthreads();

    float a0 = bk1[t], a1 = bk1[t + 32];
    #pragma unroll 8
    for (int e = 0; e < 64; ++e) {
        float rv = rows[w][e];
        a0 += rv * ws[e * 64 + t];
        a1 += rv * ws[e * 64 + t + 32];
    }
    g_k[base + t]      = a0;
    g_k[base + t + 32] = a1;
}

// ---------------- attention: 16 q rows/block, 256 threads, 2 blocks/SM ----------------
// smem: ks[128x68] | vs[128x68] | w1s[4096] | sc[16x132] | qs[16x68]  = 24704 floats
constexpr int AS_K  = 0;
constexpr int AS_V  = 128 * 68;                 // 8704
constexpr int AS_W1 = AS_V + 128 * 68;          // 17408
constexpr int AS_SC = AS_W1 + 4096;             // 21504
constexpr int AS_QS = AS_SC + 16 * 132;         // 23616
constexpr int ATTN_SMEM = (AS_QS + 16 * 68) * 4;   // 98816 B

__global__ __launch_bounds__(256, 2)
void attn_kernel(const float* __restrict__ Q, const float* __restrict__ Kp,
                 const float* __restrict__ Vsrc,
                 const float* __restrict__ wvo, const float* __restrict__ bvo,
                 float* scores_out, float* val_out, float* val_out2,
                 const float* __restrict__ wq2, const float* __restrict__ bq2,
                 float* __restrict__ q2_out) {
    extern __shared__ float asmem[];
    float* ks  = asmem + AS_K;
    float* vs  = asmem + AS_V;
    float* w1s = asmem + AS_W1;
    float* sc  = asmem + AS_SC;
    float* qs  = asmem + AS_QS;
    const int t = threadIdx.x;
    const int b = blockIdx.y, qt = blockIdx.x;
    const int q0 = qt * 16;
    const int q = t >> 4, jg = t & 15;     // 16 q-rows x 16 threads

    // ---- single load phase ----
    const float* Qb = Q + b * 8192 + q0 * 64;
    for (int idx = t; idx < 1024; idx += 256) qs[(idx >> 6) * 68 + (idx & 63)] = Qb[idx];
    const float* Kb = Kp + b * 8192;
    const float* Vb = Vsrc + b * 8192;
    for (int idx = t; idx < 8192; idx += 256) {
        ks[(idx >> 6) * 68 + (idx & 63)] = Kb[idx];
        vs[(idx >> 6) * 68 + (idx & 63)] = Vb[idx];
    }
    for (int idx = t; idx < 4096; idx += 256) w1s[idx] = wvo[idx];
    __syncthreads();

    // ---- phase 1: scores + softmax. 16 threads/q-row, 8 k's each ----
    float acc[8];
    #pragma unroll
    for (int rep = 0; rep < 8; ++rep) acc[rep] = 0.f;
    #pragma unroll
    for (int e4 = 0; e4 < 16; ++e4) {
        float4 qv = *(const float4*)&qs[q * 68 + e4 * 4];
        #pragma unroll
        for (int rep = 0; rep < 8; ++rep) {
            float4 kvv = *(const float4*)&ks[(jg + 16 * rep) * 68 + e4 * 4];
            acc[rep] += qv.x * kvv.x + qv.y * kvv.y + qv.z * kvv.z + qv.w * kvv.w;
        }
    }
    float m = -1e30f;
    #pragma unroll
    for (int rep = 0; rep < 8; ++rep) { acc[rep] *= 0.125f; m = fmaxf(m, acc[rep]); }
    #pragma unroll
    for (int off = 1; off < 16; off <<= 1) m = fmaxf(m, __shfl_xor_sync(0xffffffffu, m, off));
    float ssum = 0.f;
    #pragma unroll
    for (int rep = 0; rep < 8; ++rep) { acc[rep] = __expf(acc[rep] - m); ssum += acc[rep]; }
    #pragma unroll
    for (int off = 1; off < 16; off <<= 1) ssum += __shfl_xor_sync(0xffffffffu, ssum, off);
    const float inv = 1.0f / ssum;
    float* so = scores_out ? scores_out + b * 16384 + (q0 + q) * 128 : nullptr;
    #pragma unroll
    for (int rep = 0; rep < 8; ++rep) {
        float p = acc[rep] * inv;
        sc[q * 132 + jg + 16 * rep] = p;
        if (so) so[jg + 16 * rep] = p;
    }
    __syncthreads();

    // ---- phase 2: ctx = S @ V. 16 threads/q, 4 d's each ----
    {
        float c0 = 0.f, c1 = 0.f, c2 = 0.f, c3 = 0.f;
        #pragma unroll 8
        for (int k4 = 0; k4 < 32; ++k4) {
            float4 p = *(const float4*)&sc[q * 132 + k4 * 4];
            float4 va = *(const float4*)&vs[(k4 * 4 + 0) * 68 + jg * 4];
            float4 vb = *(const float4*)&vs[(k4 * 4 + 1) * 68 + jg * 4];
            float4 vc = *(const float4*)&vs[(k4 * 4 + 2) * 68 + jg * 4];
            float4 vd = *(const float4*)&vs[(k4 * 4 + 3) * 68 + jg * 4];
            c0 += p.x * va.x + p.y * vb.x + p.z * vc.x + p.w * vd.x;
            c1 += p.x * va.y + p.y * vb.y + p.z * vc.y + p.w * vd.y;
            c2 += p.x * va.z + p.y * vb.z + p.z * vc.z + p.w * vd.z;
            c3 += p.x * va.w + p.y * vb.w + p.z * vc.w + p.w * vd.w;
        }
        *(float4*)&qs[q * 68 + jg * 4] = make_float4(c0, c1, c2, c3);  // Q dead -> ctx
    }
    __syncthreads();

    // ---- phase 3: out = ctx @ wvo + bvo; wq2 streamed into dead ks meanwhile ----
    if (wq2) {
        for (int idx = t; idx < 4096; idx += 256) ks[idx] = wq2[idx];   // overlaps with FMA below
    }
    float o[4];
    #pragma unroll
    for (int i = 0; i < 4; ++i) o[i] = bvo[jg * 4 + i];
    #pragma unroll 4
    for (int d4 = 0; d4 < 16; ++d4) {
        float4 cv = *(const float4*)&qs[q * 68 + d4 * 4];
        float4 wa = *(const float4*)&w1s[(d4 * 4 + 0) * 64 + jg * 4];
        float4 wb = *(const float4*)&w1s[(d4 * 4 + 1) * 64 + jg * 4];
        float4 wc = *(const float4*)&w1s[(d4 * 4 + 2) * 64 + jg * 4];
        float4 wd = *(const float4*)&w1s[(d4 * 4 + 3) * 64 + jg * 4];
        o[0] += cv.x * wa.x + cv.y * wb.x + cv.z * wc.x + cv.w * wd.x;
        o[1] += cv.x * wa.y + cv.y * wb.y + cv.z * wc.y + cv.w * wd.y;
        o[2] += cv.x * wa.z + cv.y * wb.z + cv.z * wc.z + cv.w * wd.z;
        o[3] += cv.x * wa.w + cv.y * wb.w + cv.z * wc.w + cv.w * wd.w;
    }
    const size_t ooff = (size_t)b * 8192 + (size_t)(q0 + q) * 64 + jg * 4;
    *(float4*)&val_out[ooff] = make_float4(o[0], o[1], o[2], o[3]);
    if (val_out2) *(float4*)&val_out2[ooff] = make_float4(o[0], o[1], o[2], o[3]);

    // ---- phase 4: fused Q2 projection (wq2 now in ks) ----
    if (q2_out) {
        *(float4*)&sc[q * 68 + jg * 4] = make_float4(o[0], o[1], o[2], o[3]);
        __syncthreads();
        float o2[4];
        #pragma unroll
        for (int i = 0; i < 4; ++i) o2[i] = bq2[jg * 4 + i];
        #pragma unroll 4
        for (int d4 = 0; d4 < 16; ++d4) {
            float4 cv = *(const float4*)&sc[q * 68 + d4 * 4];
            float4 wa = *(const float4*)&ks[(d4 * 4 + 0) * 64 + jg * 4];
            float4 wb = *(const float4*)&ks[(d4 * 4 + 1) * 64 + jg * 4];
            float4 wc = *(const float4*)&ks[(d4 * 4 + 2) * 64 + jg * 4];
            float4 wd = *(const float4*)&ks[(d4 * 4 + 3) * 64 + jg * 4];
            o2[0] += cv.x * wa.x + cv.y * wb.x + cv.z * wc.x + cv.w * wd.x;
            o2[1] += cv.x * wa.y + cv.y * wb.y + cv.z * wc.y + cv.w * wd.y;
            o2[2] += cv.x * wa.z + cv.y * wb.z + cv.z * wc.z + cv.w * wd.z;
            o2[3] += cv.x * wa.w + cv.y * wb.w + cv.z * wc.w + cv.w * wd.w;
        }
        *(float4*)&q2_out[ooff] = make_float4(o2[0], o2[1], o2[2], o2[3]);
    }
}

extern "C" void kernel_launch(void* const* d_in, const int* in_sizes, int n_in,
                              void* d_out, int out_size) {
    const float* x      = (const float*)d_in[0];
    const float* W_vote = (const float*)d_in[1];
    const float* ln_g   = (const float*)d_in[2];
    const float* ln_b   = (const float*)d_in[3];
    const float* wq1 = (const float*)d_in[4];  const float* bq1 = (const float*)d_in[5];
    const float* wk1 = (const float*)d_in[6];  const float* bk1 = (const float*)d_in[7];
    const float* wv1 = (const float*)d_in[8];  const float* bv1 = (const float*)d_in[9];
    const float* wo1 = (const float*)d_in[10]; const float* bo1 = (const float*)d_in[11];
    const float* wq2 = (const float*)d_in[12]; const float* bq2 = (const float*)d_in[13];
    const float* wk2 = (const float*)d_in[14]; const float* bk2 = (const float*)d_in[15];
    const float* wv2 = (const float*)d_in[16]; const float* bv2 = (const float*)d_in[17];
    const float* wo2 = (const float*)d_in[18]; const float* bo2 = (const float*)d_in[19];
    float* out = (float*)d_out;

    float* out_diff = out;
    float* out_agg  = (out_size >= 524288)  ? out + 262144  : nullptr;
    float* out_fat  = (out_size >= 1048576) ? out + 524288  : nullptr;
    float* out_bat  = (out_size >= 1572864) ? out + 1048576 : nullptr;

    static int smem_set = 0;
    if (!smem_set) {
        cudaFuncSetAttribute(fat_kernel,
                             cudaFuncAttributeMaxDynamicSharedMemorySize, GEMM_SMEM);
        cudaFuncSetAttribute(attn_kernel,
                             cudaFuncAttributeMaxDynamicSharedMemorySize, ATTN_SMEM);
        smem_set = 1;
    }

    float *p_q, *p_k, *p_k2, *p_agg, *p_wvo, *p_bvo;
    cudaGetSymbolAddress((void**)&p_q,   g_q);
    cudaGetSymbolAddress((void**)&p_k,   g_k);
    cudaGetSymbolAddress((void**)&p_k2,  g_k2);
    cudaGetSymbolAddress((void**)&p_agg, g_agg);
    cudaGetSymbolAddress((void**)&p_wvo, g_wvo);
    cudaGetSymbolAddress((void**)&p_bvo, g_bvo);

    // 1) fat kernel: bf16 GEMM (y=0..3) + Q1/K2 projections + wvo folds (y=4)
    fat_kernel<<<dim3(32, 5), 512, GEMM_SMEM>>>(x, W_vote, wq1, bq1, wk2, bk2,
                                                wv1, wo1, bv1, bo1,
                                                wv2, wo2, bv2, bo2);
    // 2) fused reduce + layernorm + K1 projection
    ln_k1_kernel<<<512, 256>>>(ln_g, ln_b, wk1, bk1);
    // 3) forward attention (+ fused Q2 projection into p_q); 2 blocks/SM
    attn_kernel<<<dim3(8, 32), 256, ATTN_SMEM>>>(p_q, p_k, x, p_wvo, p_bvo,
                                                 out_fat, p_agg, out_agg,
                                                 wq2, bq2, p_q);
    // 4) feedback attention (ncu capture slot): 11 args, last four null
    attn_kernel<<<dim3(8, 32), 256, ATTN_SMEM>>>(p_q, p_k2, p_agg,
                                                 p_wvo + 4096, p_bvo + 64,
                                                 out_bat, out_diff,
                                                 nullptr, nullptr, nullptr, nullptr);
}